// round 1
// baseline (speedup 1.0000x reference)
#include <cuda_runtime.h>
#include <math.h>

#define BB 32
#define KPTS 2048
#define CFEAT 256
#define NPROP 256
#define NSAMP 16
#define NCOL 4096      // NPROP*NSAMP per batch
#define K1P 272        // 259 padded to multiple of 16
#define OUTD 119

// ---------------- scratch (static device allocations) ----------------
__device__ float d_featT[(size_t)BB*KPTS*CFEAT];      // (B, K, C)
__device__ float d_Xt  [(size_t)BB*NCOL*K1P];         // (B, 4096, 272)
__device__ float d_act1[(size_t)BB*NCOL*CFEAT];
__device__ float d_act2[(size_t)BB*NCOL*CFEAT];
__device__ float d_act3[(size_t)BB*NCOL*CFEAT];
__device__ float d_y   [(size_t)BB*NPROP*CFEAT];      // (B, 256, 256) row=prop
__device__ float d_py1 [(size_t)BB*NPROP*CFEAT];
__device__ float d_py2 [(size_t)BB*NPROP*CFEAT];
__device__ float d_net [(size_t)BB*NPROP*128];        // ldc=128, 119 used
__device__ float d_newxyz[BB*NPROP*3];
__device__ int   d_idxbuf[BB*NPROP*NSAMP];
__device__ float d_w1p[256*K1P];
__device__ float d_sb[5*2*256];                       // per layer: scale[256], bias[256]

// ---------------- output layout offsets (flattened tuple concat) -----
#define OFF_OBJ    0LL
#define OFF_CENTER 16384LL
#define OFF_SSC    40960LL
#define OFF_SRES   188416LL
#define OFF_PSIZE  630784LL
#define OFF_SEM    655360LL
#define OFF_CORN   802816LL
#define OFF_SLOG   999424LL
#define OFF_OPROB  1155072LL
#define OFF_SPROB  1163264LL

// ---------------- small prep kernels ----------------
__global__ void pad_w1_kernel(const float* __restrict__ w1) {
    int idx = blockIdx.x * 256 + threadIdx.x;          // < 256*272
    int o = idx / K1P, k = idx - o * K1P;
    d_w1p[idx] = (k < 259) ? w1[o * 259 + k] : 0.0f;
}

__global__ void sb_kernel(const float* __restrict__ sg, const float* __restrict__ sbe,
                          const float* __restrict__ sm, const float* __restrict__ sv,
                          const float* __restrict__ pg, const float* __restrict__ pb,
                          const float* __restrict__ pm, const float* __restrict__ pv) {
    int l = blockIdx.x, t = threadIdx.x;
    float g, bt, m, v;
    if (l < 3) { g = sg[l*256+t]; bt = sbe[l*256+t]; m = sm[l*256+t]; v = sv[l*256+t]; }
    else { int q = l - 3; g = pg[q*256+t]; bt = pb[q*256+t]; m = pm[q*256+t]; v = pv[q*256+t]; }
    float s = g / sqrtf(v + 1e-5f);
    d_sb[l*512 + t] = s;
    d_sb[l*512 + 256 + t] = bt - m * s;
}

// ---------------- FPS: one block per batch ----------------
__global__ __launch_bounds__(256) void fps_kernel(const float* __restrict__ xyz) {
    __shared__ float sx[KPTS], sy[KPTS], sz[KPTS];
    __shared__ float wv_s[8];
    __shared__ int   wi_s[8];
    __shared__ int   sfar;
    int b = blockIdx.x, tid = threadIdx.x;
    const float* base = xyz + (size_t)b * KPTS * 3;
    for (int k = tid; k < KPTS; k += 256) {
        sx[k] = base[k*3+0]; sy[k] = base[k*3+1]; sz[k] = base[k*3+2];
    }
    float dreg[8];
    #pragma unroll
    for (int j = 0; j < 8; j++) dreg[j] = 1e10f;
    int far = 0;
    __syncthreads();
    for (int i = 0; i < NPROP; i++) {
        float cx = sx[far], cy = sy[far], cz = sz[far];
        if (tid == 0) {
            d_newxyz[(b*NPROP+i)*3+0] = cx;
            d_newxyz[(b*NPROP+i)*3+1] = cy;
            d_newxyz[(b*NPROP+i)*3+2] = cz;
        }
        float bv = -1.0f; int bi = 0x7fffffff;
        #pragma unroll
        for (int j = 0; j < 8; j++) {
            int k = tid + j * 256;
            float dx = sx[k]-cx, dy = sy[k]-cy, dz = sz[k]-cz;
            float d = __fadd_rn(__fadd_rn(__fmul_rn(dx,dx), __fmul_rn(dy,dy)), __fmul_rn(dz,dz));
            dreg[j] = fminf(dreg[j], d);
            if (dreg[j] > bv) { bv = dreg[j]; bi = k; }
        }
        #pragma unroll
        for (int off = 16; off; off >>= 1) {
            float ov = __shfl_down_sync(0xffffffffu, bv, off);
            int   oi = __shfl_down_sync(0xffffffffu, bi, off);
            if (ov > bv || (ov == bv && oi < bi)) { bv = ov; bi = oi; }
        }
        int warp = tid >> 5, lane = tid & 31;
        if (lane == 0) { wv_s[warp] = bv; wi_s[warp] = bi; }
        __syncthreads();
        if (warp == 0) {
            float v = (lane < 8) ? wv_s[lane] : -1.0f;
            int   ii = (lane < 8) ? wi_s[lane] : 0x7fffffff;
            #pragma unroll
            for (int off = 4; off; off >>= 1) {
                float ov = __shfl_down_sync(0xffffffffu, v, off);
                int   oi = __shfl_down_sync(0xffffffffu, ii, off);
                if (ov > v || (ov == v && oi < ii)) { v = ov; ii = oi; }
            }
            if (lane == 0) sfar = ii;
        }
        __syncthreads();
        far = sfar;
    }
}

// ---------------- ball query: one block per batch, one thread per prop -----
__global__ __launch_bounds__(256) void bq_kernel(const float* __restrict__ xyz) {
    __shared__ float sx[KPTS], sy[KPTS], sz[KPTS];
    int b = blockIdx.x, tid = threadIdx.x;
    const float* base = xyz + (size_t)b * KPTS * 3;
    for (int k = tid; k < KPTS; k += 256) {
        sx[k] = base[k*3+0]; sy[k] = base[k*3+1]; sz[k] = base[k*3+2];
    }
    __syncthreads();
    int p = tid;
    float nx = d_newxyz[(b*NPROP+p)*3+0];
    float ny = d_newxyz[(b*NPROP+p)*3+1];
    float nz = d_newxyz[(b*NPROP+p)*3+2];
    int* dst = d_idxbuf + (b*NPROP+p)*NSAMP;
    int cnt = 0, first = 0;
    const float R2 = 0.09f;   // f32(0.09) to match JAX
    for (int k = 0; k < KPTS; k++) {
        float dx = sx[k]-nx, dy = sy[k]-ny, dz = sz[k]-nz;
        float d = __fadd_rn(__fadd_rn(__fmul_rn(dx,dx), __fmul_rn(dy,dy)), __fmul_rn(dz,dz));
        if (d < R2) {
            if (cnt == 0) first = k;
            dst[cnt] = k;
            if (++cnt == NSAMP) break;
        }
    }
    for (int j = cnt; j < NSAMP; j++) dst[j] = first;
}

// ---------------- feature transpose: (B,C,K) -> (B,K,C) ----------------
__global__ void transpose_kernel(const float* __restrict__ in) {
    __shared__ float tile[32][33];
    int b = blockIdx.z;
    int k0 = blockIdx.x * 32, c0 = blockIdx.y * 32;
    const float* src = in + (size_t)b * CFEAT * KPTS;
    float* dst = d_featT + (size_t)b * KPTS * CFEAT;
    int tx = threadIdx.x, ty = threadIdx.y;
    #pragma unroll
    for (int i = 0; i < 4; i++)
        tile[ty + i*8][tx] = src[(size_t)(c0 + ty + i*8) * KPTS + k0 + tx];
    __syncthreads();
    #pragma unroll
    for (int i = 0; i < 4; i++)
        dst[(size_t)(k0 + ty + i*8) * CFEAT + c0 + tx] = tile[tx][ty + i*8];
}

// ---------------- gather + build Xt: (B, 4096, 272) ----------------
__global__ __launch_bounds__(128) void gather_kernel(const float* __restrict__ xyz) {
    int blk = blockIdx.x;            // b*256 + p
    int b = blk >> 8;
    int tid = threadIdx.x;
    __shared__ int   ks[NSAMP];
    __shared__ float cxyz[3];
    if (tid < NSAMP) ks[tid] = d_idxbuf[blk*NSAMP + tid];
    if (tid < 3)     cxyz[tid] = d_newxyz[blk*3 + tid];
    __syncthreads();
    for (int s = 0; s < NSAMP; s++) {
        int k = ks[s];
        const float* frow = d_featT + ((size_t)b * KPTS + k) * CFEAT;
        const float* prow = xyz + ((size_t)b * KPTS + k) * 3;
        float* dst = d_Xt + ((size_t)blk * NSAMP + s) * K1P;
        for (int c = tid; c < K1P; c += 128) {
            float v;
            if (c < 3)        v = (prow[c] - cxyz[c]) / 0.3f;
            else if (c < 259) v = frow[c-3];
            else              v = 0.0f;
            dst[c] = v;
        }
    }
}

// ---------------- generic NT GEMM: out[n,o] = sum_k A[n,k]*W[o,k] ----------
// mode 0: relu(x*scale[o]+bias[o]);  mode 1: x + bias[o]
__global__ __launch_bounds__(256) void gemm_nt(
    const float* __restrict__ A, int lda, long long sA,
    const float* __restrict__ W, int ldw,
    float* __restrict__ C, int ldc, long long sC,
    int M, int K,
    const float* __restrict__ scale, const float* __restrict__ bias, int mode)
{
    __shared__ float As[16][128];
    __shared__ float Ws[16][128];
    int b = blockIdx.z;
    A += (long long)b * sA;
    C += (long long)b * sC;
    int n0 = blockIdx.x * 128;
    int m0 = blockIdx.y * 128;
    int tid = threadIdx.x;
    int tx = tid & 15;    // o dimension
    int ty = tid >> 4;    // n dimension
    float acc[8][8];
    #pragma unroll
    for (int i = 0; i < 8; i++)
        #pragma unroll
        for (int j = 0; j < 8; j++) acc[i][j] = 0.0f;

    int r  = tid >> 2;           // 0..63
    int k4 = (tid & 3) << 2;     // 0,4,8,12

    for (int kt = 0; kt < K; kt += 16) {
        #pragma unroll
        for (int it = 0; it < 2; it++) {
            int n = r + it * 64;
            float4 v = *(const float4*)(A + (long long)(n0 + n) * lda + kt + k4);
            As[k4+0][n] = v.x; As[k4+1][n] = v.y; As[k4+2][n] = v.z; As[k4+3][n] = v.w;
        }
        #pragma unroll
        for (int it = 0; it < 2; it++) {
            int o = r + it * 64;
            int go = m0 + o;
            float4 v = make_float4(0.f,0.f,0.f,0.f);
            if (go < M) v = *(const float4*)(W + (long long)go * ldw + kt + k4);
            Ws[k4+0][o] = v.x; Ws[k4+1][o] = v.y; Ws[k4+2][o] = v.z; Ws[k4+3][o] = v.w;
        }
        __syncthreads();
        #pragma unroll
        for (int kk = 0; kk < 16; kk++) {
            float4 a0 = *(const float4*)&As[kk][ty*8];
            float4 a1 = *(const float4*)&As[kk][ty*8+4];
            float4 w0 = *(const float4*)&Ws[kk][tx*8];
            float4 w1 = *(const float4*)&Ws[kk][tx*8+4];
            float av[8] = {a0.x,a0.y,a0.z,a0.w,a1.x,a1.y,a1.z,a1.w};
            float wv[8] = {w0.x,w0.y,w0.z,w0.w,w1.x,w1.y,w1.z,w1.w};
            #pragma unroll
            for (int i = 0; i < 8; i++)
                #pragma unroll
                for (int j = 0; j < 8; j++)
                    acc[i][j] += av[i] * wv[j];
        }
        __syncthreads();
    }
    #pragma unroll
    for (int i = 0; i < 8; i++) {
        long long n = n0 + ty*8 + i;
        float* crow = C + n * ldc;
        #pragma unroll
        for (int j = 0; j < 8; j++) {
            int o = m0 + tx*8 + j;
            if (o < M) {
                float v = acc[i][j];
                if (mode == 0) { v = fmaxf(v * scale[o] + bias[o], 0.0f); }
                else           { v = v + bias[o]; }
                crow[o] = v;
            }
        }
    }
}

// ---------------- max over 16 samples ----------------
__global__ __launch_bounds__(256) void maxpool_kernel() {
    int blk = blockIdx.x;           // b*256 + p
    int c = threadIdx.x;
    const float* src = d_act3 + (size_t)blk * NSAMP * CFEAT;
    float m = src[c];
    #pragma unroll
    for (int s = 1; s < NSAMP; s++) m = fmaxf(m, src[s*CFEAT + c]);
    d_y[(size_t)blk * CFEAT + c] = m;
}

// ---------------- decode head ----------------
__global__ __launch_bounds__(256) void decode_kernel(const float* __restrict__ msa,
                                                     float* __restrict__ out) {
    int g = blockIdx.x * 256 + threadIdx.x;    // 0..8191
    if (g >= BB * NPROP) return;
    const float* nt = d_net + (size_t)g * 128;
    const float* nx = d_newxyz + (size_t)g * 3;

    float obj0 = nt[0], obj1 = nt[1];
    out[OFF_OBJ + 2*g + 0] = obj0;
    out[OFF_OBJ + 2*g + 1] = obj1;

    float cen[3];
    #pragma unroll
    for (int c = 0; c < 3; c++) {
        cen[c] = nx[c] + nt[2 + c];
        out[OFF_CENTER + 3*g + c] = cen[c];
    }

    // size scores + first-argmax
    float bestv = -1e30f; int best = 0;
    #pragma unroll
    for (int j = 0; j < 18; j++) {
        float s = nt[29 + j];
        out[OFF_SSC + 18*g + j] = s;
        if (s > bestv) { bestv = s; best = j; }
    }

    // size residuals
    #pragma unroll
    for (int j = 0; j < 18; j++)
        #pragma unroll
        for (int c = 0; c < 3; c++)
            out[OFF_SRES + 54*g + j*3 + c] = nt[47 + j*3 + c] * msa[j*3 + c];

    float ps[3];
    #pragma unroll
    for (int c = 0; c < 3; c++) {
        ps[c] = nt[47 + best*3 + c] * msa[best*3 + c] + msa[best*3 + c];
        out[OFF_PSIZE + 3*g + c] = ps[c];
    }

    // semantics + softmax
    float mx = -1e30f;
    #pragma unroll
    for (int j = 0; j < 18; j++) {
        float s = nt[101 + j];
        out[OFF_SEM  + 18*g + j] = s;
        out[OFF_SLOG + 19*g + j] = s;
        mx = fmaxf(mx, s);
    }
    float e[18], sum = 0.0f;
    #pragma unroll
    for (int j = 0; j < 18; j++) { e[j] = expf(nt[101 + j] - mx); sum += e[j]; }
    #pragma unroll
    for (int j = 0; j < 18; j++) out[OFF_SPROB + 18*g + j] = e[j] / sum;

    out[OFF_SLOG + 19*g + 18] = (obj0 <= obj1) ? 0.0f : 1e10f;

    float m2 = fmaxf(obj0, obj1);
    float e0 = expf(obj0 - m2), e1 = expf(obj1 - m2);
    out[OFF_OPROB + g] = e1 / (e0 + e1);

    // corners (angle = 0 -> identity rotation)
    float cc0 = cen[0], cc1 = cen[2], cc2 = -cen[1];
    const float sxv[8] = {1,1,-1,-1,1,1,-1,-1};
    const float syv[8] = {1,1,1,1,-1,-1,-1,-1};
    const float szv[8] = {1,-1,-1,1,1,-1,-1,1};
    #pragma unroll
    for (int k = 0; k < 8; k++) {
        out[OFF_CORN + 24*g + k*3 + 0] = cc0 + ps[0] * sxv[k] * 0.5f;
        out[OFF_CORN + 24*g + k*3 + 1] = cc1 + ps[2] * syv[k] * 0.5f;
        out[OFF_CORN + 24*g + k*3 + 2] = cc2 + ps[1] * szv[k] * 0.5f;
    }
}

// ---------------- launch ----------------
extern "C" void kernel_launch(void* const* d_in, const int* in_sizes, int n_in,
                              void* d_out, int out_size) {
    const float* xyz      = (const float*)d_in[0];
    const float* features = (const float*)d_in[1];
    const float* sa_w1    = (const float*)d_in[2];
    const float* sa_w2    = (const float*)d_in[3];
    const float* sa_w3    = (const float*)d_in[4];
    const float* sa_gamma = (const float*)d_in[5];
    const float* sa_beta  = (const float*)d_in[6];
    const float* sa_mean  = (const float*)d_in[7];
    const float* sa_var   = (const float*)d_in[8];
    const float* p_w1     = (const float*)d_in[9];
    const float* p_w2     = (const float*)d_in[10];
    const float* p_w3     = (const float*)d_in[11];
    const float* p_b3     = (const float*)d_in[12];
    const float* p_gamma  = (const float*)d_in[13];
    const float* p_beta   = (const float*)d_in[14];
    const float* p_mean   = (const float*)d_in[15];
    const float* p_var    = (const float*)d_in[16];
    const float* msa      = (const float*)d_in[17];
    float* out = (float*)d_out;

    void *pXt, *pA1, *pA2, *pA3, *pY, *pP1, *pP2, *pNet, *pW1p, *pSb;
    cudaGetSymbolAddress(&pXt,  d_Xt);
    cudaGetSymbolAddress(&pA1,  d_act1);
    cudaGetSymbolAddress(&pA2,  d_act2);
    cudaGetSymbolAddress(&pA3,  d_act3);
    cudaGetSymbolAddress(&pY,   d_y);
    cudaGetSymbolAddress(&pP1,  d_py1);
    cudaGetSymbolAddress(&pP2,  d_py2);
    cudaGetSymbolAddress(&pNet, d_net);
    cudaGetSymbolAddress(&pW1p, d_w1p);
    cudaGetSymbolAddress(&pSb,  d_sb);
    float* Xt  = (float*)pXt;   float* A1 = (float*)pA1;  float* A2 = (float*)pA2;
    float* A3  = (float*)pA3;   float* Y  = (float*)pY;   float* P1 = (float*)pP1;
    float* P2  = (float*)pP2;   float* NET = (float*)pNet;
    float* W1P = (float*)pW1p;  float* SB = (float*)pSb;

    pad_w1_kernel<<<272, 256>>>(sa_w1);
    sb_kernel<<<5, 256>>>(sa_gamma, sa_beta, sa_mean, sa_var,
                          p_gamma, p_beta, p_mean, p_var);
    fps_kernel<<<BB, 256>>>(xyz);
    bq_kernel<<<BB, 256>>>(xyz);
    transpose_kernel<<<dim3(KPTS/32, CFEAT/32, BB), dim3(32, 8)>>>(features);
    gather_kernel<<<BB*NPROP, 128>>>(xyz);

    // SA layer 1: (4096 x 272) x (256 x 272)^T
    gemm_nt<<<dim3(NCOL/128, 2, BB), 256>>>(Xt, K1P, (long long)NCOL*K1P,
        W1P, K1P, A1, CFEAT, (long long)NCOL*CFEAT, 256, K1P,
        SB + 0*512, SB + 0*512 + 256, 0);
    // SA layer 2
    gemm_nt<<<dim3(NCOL/128, 2, BB), 256>>>(A1, CFEAT, (long long)NCOL*CFEAT,
        sa_w2, CFEAT, A2, CFEAT, (long long)NCOL*CFEAT, 256, CFEAT,
        SB + 1*512, SB + 1*512 + 256, 0);
    // SA layer 3
    gemm_nt<<<dim3(NCOL/128, 2, BB), 256>>>(A2, CFEAT, (long long)NCOL*CFEAT,
        sa_w3, CFEAT, A3, CFEAT, (long long)NCOL*CFEAT, 256, CFEAT,
        SB + 2*512, SB + 2*512 + 256, 0);

    maxpool_kernel<<<BB*NPROP, 256>>>();

    // proposal layer 1
    gemm_nt<<<dim3(NPROP/128, 2, BB), 256>>>(Y, CFEAT, (long long)NPROP*CFEAT,
        p_w1, CFEAT, P1, CFEAT, (long long)NPROP*CFEAT, 256, CFEAT,
        SB + 3*512, SB + 3*512 + 256, 0);
    // proposal layer 2
    gemm_nt<<<dim3(NPROP/128, 2, BB), 256>>>(P1, CFEAT, (long long)NPROP*CFEAT,
        p_w2, CFEAT, P2, CFEAT, (long long)NPROP*CFEAT, 256, CFEAT,
        SB + 4*512, SB + 4*512 + 256, 0);
    // head: M=119, +bias only
    gemm_nt<<<dim3(NPROP/128, 1, BB), 256>>>(P2, CFEAT, (long long)NPROP*CFEAT,
        p_w3, CFEAT, NET, 128, (long long)NPROP*128, OUTD, CFEAT,
        SB, p_b3, 1);

    decode_kernel<<<BB, 256>>>(msa, out);
}

// round 6
// speedup vs baseline: 1.2986x; 1.2986x over previous
#include <cuda_runtime.h>
#include <math.h>
#include <stdint.h>

#define BB 32
#define KPTS 2048
#define CFEAT 256
#define NPROP 256
#define NSAMP 16
#define NCOL 4096      // NPROP*NSAMP per batch
#define K1P 288        // 259 padded to multiple of 32
#define OUTD 119
#define TOTROW (BB*NCOL)    // 131072
#define PROPROW (BB*NPROP)  // 8192
#define SAS 36              // smem tile stride (floats)
#define TILE_F (128*SAS)    // floats per tile
#define GEMM_SMEM ((4*TILE_F + 256) * 4)   // hi/lo x A/B + scale/bias

// ---------------- scratch (static device allocations) ----------------
__device__ float d_featT[(size_t)BB*KPTS*CFEAT];      // (B, K, C)
__device__ float d_Xt  [(size_t)BB*NCOL*K1P];         // (B, 4096, 288)
__device__ float d_act1[(size_t)BB*NCOL*CFEAT];
__device__ float d_act2[(size_t)BB*NCOL*CFEAT];
__device__ float d_act3[(size_t)BB*NCOL*CFEAT];
__device__ float d_y   [(size_t)BB*NPROP*CFEAT];
__device__ float d_py1 [(size_t)BB*NPROP*CFEAT];
__device__ float d_py2 [(size_t)BB*NPROP*CFEAT];
__device__ float d_net [(size_t)BB*NPROP*128];        // ldc=128, 119 used
__device__ float d_newxyz[BB*NPROP*3];
__device__ int   d_idxbuf[BB*NPROP*NSAMP];
__device__ float d_w1p[256*K1P];
__device__ float d_w3p[128*256];
__device__ float d_b3p[128];
__device__ float d_sb[5*2*256];                       // per layer: scale[256], bias[256]
__device__ float d_one[256];                          // dummy scale for mode 1

// ---------------- output layout offsets (flattened tuple concat) -----
#define OFF_OBJ    0LL
#define OFF_CENTER 16384LL
#define OFF_SSC    40960LL
#define OFF_SRES   188416LL
#define OFF_PSIZE  630784LL
#define OFF_SEM    655360LL
#define OFF_CORN   802816LL
#define OFF_SLOG   999424LL
#define OFF_OPROB  1155072LL
#define OFF_SPROB  1163264LL

__device__ __forceinline__ uint32_t f2tf(float x) {
    uint32_t r; asm("cvt.rna.tf32.f32 %0, %1;" : "=r"(r) : "f"(x)); return r;
}

__device__ __forceinline__ void mma_tf32(float* c, const uint32_t* a,
                                         uint32_t b0, uint32_t b1) {
    asm volatile(
        "mma.sync.aligned.m16n8k8.row.col.f32.tf32.tf32.f32 "
        "{%0,%1,%2,%3}, {%4,%5,%6,%7}, {%8,%9}, {%0,%1,%2,%3};"
        : "+f"(c[0]), "+f"(c[1]), "+f"(c[2]), "+f"(c[3])
        : "r"(a[0]), "r"(a[1]), "r"(a[2]), "r"(a[3]), "r"(b0), "r"(b1));
}

// ============ 3xTF32 GEMM: C[n,o] = sum_k A[n,k] * W[o,k] (~fp32 acc) =======
// CTA tile 128x128, K chunk 32. mode 0: relu(x*scale+bias); mode 1: x+bias
__global__ __launch_bounds__(256) void gemm_mma(
    const float* __restrict__ A, int lda,
    const float* __restrict__ W, int ldw,
    float* __restrict__ C, int ldc,
    int nchunk,
    const float* __restrict__ scale, const float* __restrict__ bias, int mode)
{
    extern __shared__ float sm[];
    float* Ah = sm;                 // hi tiles
    float* Bh = sm + TILE_F;
    float* Al = sm + 2*TILE_F;      // lo tiles
    float* Bl = sm + 3*TILE_F;
    float* s_s = sm + 4*TILE_F;
    float* s_b = s_s + 128;

    const int tid = threadIdx.x;
    const int lane = tid & 31, wid = tid >> 5;
    const int wm = wid & 3, wn = wid >> 2;      // 4 x 2 warp grid
    const long long m0 = (long long)blockIdx.x * 128;
    const int y0 = blockIdx.y * 128;
    const int lq = lane >> 2;                   // 0..7
    const int lr = lane & 3;                    // 0..3

    if (tid < 128) {
        s_s[tid] = (mode == 0) ? scale[y0 + tid] : 1.0f;
        s_b[tid] = bias[y0 + tid];
    }

    float acc[2][8][4];
    #pragma unroll
    for (int mt = 0; mt < 2; mt++)
        #pragma unroll
        for (int nt = 0; nt < 8; nt++)
            #pragma unroll
            for (int j = 0; j < 4; j++) acc[mt][nt][j] = 0.0f;

    const int srow = tid >> 3;      // 0..31
    const int sq   = tid & 7;       // float4 slot

    for (int kc = 0; kc < nchunk; kc++) {
        const int kt = kc * 32;
        __syncthreads();
        #pragma unroll
        for (int it = 0; it < 4; it++) {
            int row = srow + it * 32;
            int so = row * SAS + sq * 4;
            float4 v = *(const float4*)(A + (m0 + row) * lda + kt + sq * 4);
            uint4 h = make_uint4(f2tf(v.x), f2tf(v.y), f2tf(v.z), f2tf(v.w));
            uint4 l = make_uint4(f2tf(v.x - __uint_as_float(h.x)),
                                 f2tf(v.y - __uint_as_float(h.y)),
                                 f2tf(v.z - __uint_as_float(h.z)),
                                 f2tf(v.w - __uint_as_float(h.w)));
            *(uint4*)&Ah[so] = h;
            *(uint4*)&Al[so] = l;
            float4 w = *(const float4*)(W + (long long)(y0 + row) * ldw + kt + sq * 4);
            uint4 wh = make_uint4(f2tf(w.x), f2tf(w.y), f2tf(w.z), f2tf(w.w));
            uint4 wl = make_uint4(f2tf(w.x - __uint_as_float(wh.x)),
                                  f2tf(w.y - __uint_as_float(wh.y)),
                                  f2tf(w.z - __uint_as_float(wh.z)),
                                  f2tf(w.w - __uint_as_float(wh.w)));
            *(uint4*)&Bh[so] = wh;
            *(uint4*)&Bl[so] = wl;
        }
        __syncthreads();
        #pragma unroll
        for (int k8 = 0; k8 < 4; k8++) {
            const int kk = k8 * 8 + lr;
            uint32_t ah[2][4], al[2][4];
            #pragma unroll
            for (int mt = 0; mt < 2; mt++) {
                int r = wm * 32 + mt * 16 + lq;
                ah[mt][0] = __float_as_uint(Ah[r * SAS + kk]);
                ah[mt][1] = __float_as_uint(Ah[(r + 8) * SAS + kk]);
                ah[mt][2] = __float_as_uint(Ah[r * SAS + kk + 4]);
                ah[mt][3] = __float_as_uint(Ah[(r + 8) * SAS + kk + 4]);
                al[mt][0] = __float_as_uint(Al[r * SAS + kk]);
                al[mt][1] = __float_as_uint(Al[(r + 8) * SAS + kk]);
                al[mt][2] = __float_as_uint(Al[r * SAS + kk + 4]);
                al[mt][3] = __float_as_uint(Al[(r + 8) * SAS + kk + 4]);
            }
            #pragma unroll
            for (int nt = 0; nt < 8; nt++) {
                int o = wn * 64 + nt * 8 + lq;
                uint32_t bh0 = __float_as_uint(Bh[o * SAS + kk]);
                uint32_t bh1 = __float_as_uint(Bh[o * SAS + kk + 4]);
                uint32_t bl0 = __float_as_uint(Bl[o * SAS + kk]);
                uint32_t bl1 = __float_as_uint(Bl[o * SAS + kk + 4]);
                #pragma unroll
                for (int mt = 0; mt < 2; mt++) {
                    mma_tf32(acc[mt][nt], al[mt], bh0, bh1);   // lo*hi
                    mma_tf32(acc[mt][nt], ah[mt], bl0, bl1);   // hi*lo
                    mma_tf32(acc[mt][nt], ah[mt], bh0, bh1);   // hi*hi
                }
            }
        }
    }

    // epilogue
    #pragma unroll
    for (int mt = 0; mt < 2; mt++) {
        long long r0 = m0 + wm * 32 + mt * 16 + lq;
        #pragma unroll
        for (int nt = 0; nt < 8; nt++) {
            int gc = wn * 64 + nt * 8 + 2 * lr;        // local col 0..127
            float s0 = s_s[gc], s1 = s_s[gc + 1];
            float bb0 = s_b[gc], bb1 = s_b[gc + 1];
            float2 v0, v1;
            v0.x = acc[mt][nt][0] * s0 + bb0;
            v0.y = acc[mt][nt][1] * s1 + bb1;
            v1.x = acc[mt][nt][2] * s0 + bb0;
            v1.y = acc[mt][nt][3] * s1 + bb1;
            if (mode == 0) {
                v0.x = fmaxf(v0.x, 0.f); v0.y = fmaxf(v0.y, 0.f);
                v1.x = fmaxf(v1.x, 0.f); v1.y = fmaxf(v1.y, 0.f);
            }
            *(float2*)(C + r0 * ldc + y0 + gc) = v0;
            *(float2*)(C + (r0 + 8) * ldc + y0 + gc) = v1;
        }
    }
}

// ---------------- small prep kernels ----------------
__global__ void pad_w1_kernel(const float* __restrict__ w1) {
    int idx = blockIdx.x * 256 + threadIdx.x;          // < 256*288
    int o = idx / K1P, k = idx - o * K1P;
    d_w1p[idx] = (k < 259) ? w1[o * 259 + k] : 0.0f;
}

__global__ void pad_w3_kernel(const float* __restrict__ w3) {
    int o = blockIdx.x, k = threadIdx.x;               // 128 x 256
    d_w3p[o * 256 + k] = (o < OUTD) ? w3[o * 256 + k] : 0.0f;
}

__global__ void sb_kernel(const float* __restrict__ sg, const float* __restrict__ sbe,
                          const float* __restrict__ sm, const float* __restrict__ sv,
                          const float* __restrict__ pg, const float* __restrict__ pb,
                          const float* __restrict__ pm, const float* __restrict__ pv,
                          const float* __restrict__ b3) {
    int l = blockIdx.x, t = threadIdx.x;
    if (l == 5) {
        if (t < 128) d_b3p[t] = (t < OUTD) ? b3[t] : 0.0f;
        d_one[t] = 1.0f;
        return;
    }
    float g, bt, m, v;
    if (l < 3) { g = sg[l*256+t]; bt = sbe[l*256+t]; m = sm[l*256+t]; v = sv[l*256+t]; }
    else { int q = l - 3; g = pg[q*256+t]; bt = pb[q*256+t]; m = pm[q*256+t]; v = pv[q*256+t]; }
    float s = g / sqrtf(v + 1e-5f);
    d_sb[l*512 + t] = s;
    d_sb[l*512 + 256 + t] = bt - m * s;
}

// ---------------- FPS: one block per batch ----------------
__global__ __launch_bounds__(256) void fps_kernel(const float* __restrict__ xyz) {
    __shared__ float sx[KPTS], sy[KPTS], sz[KPTS];
    __shared__ float wv_s[8];
    __shared__ int   wi_s[8];
    __shared__ int   sfar;
    int b = blockIdx.x, tid = threadIdx.x;
    const float* base = xyz + (size_t)b * KPTS * 3;
    for (int k = tid; k < KPTS; k += 256) {
        sx[k] = base[k*3+0]; sy[k] = base[k*3+1]; sz[k] = base[k*3+2];
    }
    float dreg[8];
    #pragma unroll
    for (int j = 0; j < 8; j++) dreg[j] = 1e10f;
    int far = 0;
    __syncthreads();
    for (int i = 0; i < NPROP; i++) {
        float cx = sx[far], cy = sy[far], cz = sz[far];
        if (tid == 0) {
            d_newxyz[(b*NPROP+i)*3+0] = cx;
            d_newxyz[(b*NPROP+i)*3+1] = cy;
            d_newxyz[(b*NPROP+i)*3+2] = cz;
        }
        float bv = -1.0f; int bi = 0x7fffffff;
        #pragma unroll
        for (int j = 0; j < 8; j++) {
            int k = tid + j * 256;
            float dx = sx[k]-cx, dy = sy[k]-cy, dz = sz[k]-cz;
            float d = __fadd_rn(__fadd_rn(__fmul_rn(dx,dx), __fmul_rn(dy,dy)), __fmul_rn(dz,dz));
            dreg[j] = fminf(dreg[j], d);
            if (dreg[j] > bv) { bv = dreg[j]; bi = k; }
        }
        #pragma unroll
        for (int off = 16; off; off >>= 1) {
            float ov = __shfl_down_sync(0xffffffffu, bv, off);
            int   oi = __shfl_down_sync(0xffffffffu, bi, off);
            if (ov > bv || (ov == bv && oi < bi)) { bv = ov; bi = oi; }
        }
        int warp = tid >> 5, lane = tid & 31;
        if (lane == 0) { wv_s[warp] = bv; wi_s[warp] = bi; }
        __syncthreads();
        if (warp == 0) {
            float v = (lane < 8) ? wv_s[lane] : -1.0f;
            int   ii = (lane < 8) ? wi_s[lane] : 0x7fffffff;
            #pragma unroll
            for (int off = 4; off; off >>= 1) {
                float ov = __shfl_down_sync(0xffffffffu, v, off);
                int   oi = __shfl_down_sync(0xffffffffu, ii, off);
                if (ov > v || (ov == v && oi < ii)) { v = ov; ii = oi; }
            }
            if (lane == 0) sfar = ii;
        }
        __syncthreads();
        far = sfar;
    }
}

// ---------------- ball query ----------------
__global__ __launch_bounds__(256) void bq_kernel(const float* __restrict__ xyz) {
    __shared__ float sx[KPTS], sy[KPTS], sz[KPTS];
    int b = blockIdx.x, tid = threadIdx.x;
    const float* base = xyz + (size_t)b * KPTS * 3;
    for (int k = tid; k < KPTS; k += 256) {
        sx[k] = base[k*3+0]; sy[k] = base[k*3+1]; sz[k] = base[k*3+2];
    }
    __syncthreads();
    int p = tid;
    float nx = d_newxyz[(b*NPROP+p)*3+0];
    float ny = d_newxyz[(b*NPROP+p)*3+1];
    float nz = d_newxyz[(b*NPROP+p)*3+2];
    int* dst = d_idxbuf + (b*NPROP+p)*NSAMP;
    int cnt = 0, first = 0;
    const float R2 = 0.09f;
    for (int k = 0; k < KPTS; k++) {
        float dx = sx[k]-nx, dy = sy[k]-ny, dz = sz[k]-nz;
        float d = __fadd_rn(__fadd_rn(__fmul_rn(dx,dx), __fmul_rn(dy,dy)), __fmul_rn(dz,dz));
        if (d < R2) {
            if (cnt == 0) first = k;
            dst[cnt] = k;
            if (++cnt == NSAMP) break;
        }
    }
    for (int j = cnt; j < NSAMP; j++) dst[j] = first;
}

// ---------------- feature transpose: (B,C,K) -> (B,K,C) ----------------
__global__ void transpose_kernel(const float* __restrict__ in) {
    __shared__ float tile[32][33];
    int b = blockIdx.z;
    int k0 = blockIdx.x * 32, c0 = blockIdx.y * 32;
    const float* src = in + (size_t)b * CFEAT * KPTS;
    float* dst = d_featT + (size_t)b * KPTS * CFEAT;
    int tx = threadIdx.x, ty = threadIdx.y;
    #pragma unroll
    for (int i = 0; i < 4; i++)
        tile[ty + i*8][tx] = src[(size_t)(c0 + ty + i*8) * KPTS + k0 + tx];
    __syncthreads();
    #pragma unroll
    for (int i = 0; i < 4; i++)
        dst[(size_t)(k0 + ty + i*8) * CFEAT + c0 + tx] = tile[tx][ty + i*8];
}

// ---------------- gather + build Xt: (B, 4096, 288) ----------------
__global__ __launch_bounds__(128) void gather_kernel(const float* __restrict__ xyz) {
    int blk = blockIdx.x;            // b*256 + p
    int b = blk >> 8;
    int tid = threadIdx.x;
    __shared__ int   ks[NSAMP];
    __shared__ float cxyz[3];
    if (tid < NSAMP) ks[tid] = d_idxbuf[blk*NSAMP + tid];
    if (tid < 3)     cxyz[tid] = d_newxyz[blk*3 + tid];
    __syncthreads();
    for (int s = 0; s < NSAMP; s++) {
        int k = ks[s];
        const float* frow = d_featT + ((size_t)b * KPTS + k) * CFEAT;
        const float* prow = xyz + ((size_t)b * KPTS + k) * 3;
        float* dst = d_Xt + ((size_t)blk * NSAMP + s) * K1P;
        for (int c = tid; c < K1P; c += 128) {
            float v;
            if (c < 3)        v = (prow[c] - cxyz[c]) / 0.3f;
            else if (c < 259) v = frow[c-3];
            else              v = 0.0f;
            dst[c] = v;
        }
    }
}

// ---------------- max over 16 samples ----------------
__global__ __launch_bounds__(256) void maxpool_kernel() {
    int blk = blockIdx.x;           // b*256 + p
    int c = threadIdx.x;
    const float* src = d_act3 + (size_t)blk * NSAMP * CFEAT;
    float m = src[c];
    #pragma unroll
    for (int s = 1; s < NSAMP; s++) m = fmaxf(m, src[s*CFEAT + c]);
    d_y[(size_t)blk * CFEAT + c] = m;
}

// ---------------- decode head ----------------
__global__ __launch_bounds__(256) void decode_kernel(const float* __restrict__ msa,
                                                     float* __restrict__ out) {
    int g = blockIdx.x * 256 + threadIdx.x;    // 0..8191
    if (g >= BB * NPROP) return;
    const float* nt = d_net + (size_t)g * 128;
    const float* nx = d_newxyz + (size_t)g * 3;

    float obj0 = nt[0], obj1 = nt[1];
    out[OFF_OBJ + 2*g + 0] = obj0;
    out[OFF_OBJ + 2*g + 1] = obj1;

    float cen[3];
    #pragma unroll
    for (int c = 0; c < 3; c++) {
        cen[c] = nx[c] + nt[2 + c];
        out[OFF_CENTER + 3*g + c] = cen[c];
    }

    float bestv = -1e30f; int best = 0;
    #pragma unroll
    for (int j = 0; j < 18; j++) {
        float s = nt[29 + j];
        out[OFF_SSC + 18*g + j] = s;
        if (s > bestv) { bestv = s; best = j; }
    }

    #pragma unroll
    for (int j = 0; j < 18; j++)
        #pragma unroll
        for (int c = 0; c < 3; c++)
            out[OFF_SRES + 54*g + j*3 + c] = nt[47 + j*3 + c] * msa[j*3 + c];

    float ps[3];
    #pragma unroll
    for (int c = 0; c < 3; c++) {
        ps[c] = nt[47 + best*3 + c] * msa[best*3 + c] + msa[best*3 + c];
        out[OFF_PSIZE + 3*g + c] = ps[c];
    }

    float mx = -1e30f;
    #pragma unroll
    for (int j = 0; j < 18; j++) {
        float s = nt[101 + j];
        out[OFF_SEM  + 18*g + j] = s;
        out[OFF_SLOG + 19*g + j] = s;
        mx = fmaxf(mx, s);
    }
    float e[18], sum = 0.0f;
    #pragma unroll
    for (int j = 0; j < 18; j++) { e[j] = expf(nt[101 + j] - mx); sum += e[j]; }
    #pragma unroll
    for (int j = 0; j < 18; j++) out[OFF_SPROB + 18*g + j] = e[j] / sum;

    out[OFF_SLOG + 19*g + 18] = (obj0 <= obj1) ? 0.0f : 1e10f;

    float m2 = fmaxf(obj0, obj1);
    float e0 = expf(obj0 - m2), e1 = expf(obj1 - m2);
    out[OFF_OPROB + g] = e1 / (e0 + e1);

    float cc0 = cen[0], cc1 = cen[2], cc2 = -cen[1];
    const float sxv[8] = {1,1,-1,-1,1,1,-1,-1};
    const float syv[8] = {1,1,1,1,-1,-1,-1,-1};
    const float szv[8] = {1,-1,-1,1,1,-1,-1,1};
    #pragma unroll
    for (int k = 0; k < 8; k++) {
        out[OFF_CORN + 24*g + k*3 + 0] = cc0 + ps[0] * sxv[k] * 0.5f;
        out[OFF_CORN + 24*g + k*3 + 1] = cc1 + ps[2] * syv[k] * 0.5f;
        out[OFF_CORN + 24*g + k*3 + 2] = cc2 + ps[1] * szv[k] * 0.5f;
    }
}

// ---------------- launch ----------------
extern "C" void kernel_launch(void* const* d_in, const int* in_sizes, int n_in,
                              void* d_out, int out_size) {
    const float* xyz      = (const float*)d_in[0];
    const float* features = (const float*)d_in[1];
    const float* sa_w1    = (const float*)d_in[2];
    const float* sa_w2    = (const float*)d_in[3];
    const float* sa_w3    = (const float*)d_in[4];
    const float* sa_gamma = (const float*)d_in[5];
    const float* sa_beta  = (const float*)d_in[6];
    const float* sa_mean  = (const float*)d_in[7];
    const float* sa_var   = (const float*)d_in[8];
    const float* p_w1     = (const float*)d_in[9];
    const float* p_w2     = (const float*)d_in[10];
    const float* p_w3     = (const float*)d_in[11];
    const float* p_b3     = (const float*)d_in[12];
    const float* p_gamma  = (const float*)d_in[13];
    const float* p_beta   = (const float*)d_in[14];
    const float* p_mean   = (const float*)d_in[15];
    const float* p_var    = (const float*)d_in[16];
    const float* msa      = (const float*)d_in[17];
    float* out = (float*)d_out;

    void *pXt, *pA1, *pA2, *pA3, *pY, *pP1, *pP2, *pNet, *pW1p, *pW3p, *pB3p, *pSb, *pOne;
    cudaGetSymbolAddress(&pXt,  d_Xt);
    cudaGetSymbolAddress(&pA1,  d_act1);
    cudaGetSymbolAddress(&pA2,  d_act2);
    cudaGetSymbolAddress(&pA3,  d_act3);
    cudaGetSymbolAddress(&pY,   d_y);
    cudaGetSymbolAddress(&pP1,  d_py1);
    cudaGetSymbolAddress(&pP2,  d_py2);
    cudaGetSymbolAddress(&pNet, d_net);
    cudaGetSymbolAddress(&pW1p, d_w1p);
    cudaGetSymbolAddress(&pW3p, d_w3p);
    cudaGetSymbolAddress(&pB3p, d_b3p);
    cudaGetSymbolAddress(&pSb,  d_sb);
    cudaGetSymbolAddress(&pOne, d_one);
    float* Xt  = (float*)pXt;   float* A1 = (float*)pA1;  float* A2 = (float*)pA2;
    float* A3  = (float*)pA3;   float* Y  = (float*)pY;   float* P1 = (float*)pP1;
    float* P2  = (float*)pP2;   float* NET = (float*)pNet;
    float* W1P = (float*)pW1p;  float* W3P = (float*)pW3p;
    float* B3P = (float*)pB3p;  float* SB = (float*)pSb;
    float* ONE = (float*)pOne;

    cudaFuncSetAttribute(gemm_mma, cudaFuncAttributeMaxDynamicSharedMemorySize, GEMM_SMEM);

    pad_w1_kernel<<<K1P, 256>>>(sa_w1);
    pad_w3_kernel<<<128, 256>>>(p_w3);
    sb_kernel<<<6, 256>>>(sa_gamma, sa_beta, sa_mean, sa_var,
                          p_gamma, p_beta, p_mean, p_var, p_b3);
    fps_kernel<<<BB, 256>>>(xyz);
    bq_kernel<<<BB, 256>>>(xyz);
    transpose_kernel<<<dim3(KPTS/32, CFEAT/32, BB), dim3(32, 8)>>>(features);
    gather_kernel<<<BB*NPROP, 128>>>(xyz);

    // SA layer 1: (131072 x 288) x (256 x 288)^T
    gemm_mma<<<dim3(TOTROW/128, 2), 256, GEMM_SMEM>>>(Xt, K1P, W1P, K1P, A1, 256,
        K1P/32, SB + 0*512, SB + 0*512 + 256, 0);
    // SA layer 2
    gemm_mma<<<dim3(TOTROW/128, 2), 256, GEMM_SMEM>>>(A1, 256, sa_w2, 256, A2, 256,
        8, SB + 1*512, SB + 1*512 + 256, 0);
    // SA layer 3
    gemm_mma<<<dim3(TOTROW/128, 2), 256, GEMM_SMEM>>>(A2, 256, sa_w3, 256, A3, 256,
        8, SB + 2*512, SB + 2*512 + 256, 0);

    maxpool_kernel<<<BB*NPROP, 256>>>();

    // proposal layers
    gemm_mma<<<dim3(PROPROW/128, 2), 256, GEMM_SMEM>>>(Y, 256, p_w1, 256, P1, 256,
        8, SB + 3*512, SB + 3*512 + 256, 0);
    gemm_mma<<<dim3(PROPROW/128, 2), 256, GEMM_SMEM>>>(P1, 256, p_w2, 256, P2, 256,
        8, SB + 4*512, SB + 4*512 + 256, 0);
    // head: N=128 (119 valid), bias only
    gemm_mma<<<dim3(PROPROW/128, 1), 256, GEMM_SMEM>>>(P2, 256, W3P, 256, NET, 128,
        8, ONE, B3P, 1);

    decode_kernel<<<BB, 256>>>(msa, out);
}

// round 7
// speedup vs baseline: 1.4433x; 1.1114x over previous
#include <cuda_runtime.h>
#include <math.h>
#include <stdint.h>

#define BB 32
#define KPTS 2048
#define CFEAT 256
#define NPROP 256
#define NSAMP 16
#define NCOL 4096
#define K1P 288        // 259 padded to multiple of 32
#define OUTD 119
#define TOTROW (BB*NCOL)    // 131072
#define PROPROW (BB*NPROP)  // 8192
#define SAS 36              // A smem stride (floats)

// smem stage: Ah(4608) Al(4608) Bh(4096) Bl(4096) = 17408 floats
#define STAGEF 17408
#define GEMM_SMEM ((2*STAGEF + 256) * 4)   // 140288 bytes

// ---------------- scratch ----------------
__device__ float d_featT[(size_t)BB*KPTS*CFEAT];
__device__ float d_xth[(size_t)TOTROW*K1P];
__device__ float d_xtl[(size_t)TOTROW*K1P];
__device__ float d_a1h[(size_t)TOTROW*CFEAT];
__device__ float d_a1l[(size_t)TOTROW*CFEAT];
__device__ float d_a2h[(size_t)TOTROW*CFEAT];
__device__ float d_a2l[(size_t)TOTROW*CFEAT];
__device__ float d_act3[(size_t)TOTROW*CFEAT];
__device__ float d_yh [(size_t)PROPROW*CFEAT];
__device__ float d_yl [(size_t)PROPROW*CFEAT];
__device__ float d_p1h[(size_t)PROPROW*CFEAT];
__device__ float d_p1l[(size_t)PROPROW*CFEAT];
__device__ float d_p2h[(size_t)PROPROW*CFEAT];
__device__ float d_p2l[(size_t)PROPROW*CFEAT];
__device__ float d_net[(size_t)PROPROW*128];
__device__ float d_newxyz[PROPROW*3];
__device__ int   d_idxbuf[PROPROW*NSAMP];
__device__ float d_sb[5*2*256];
__device__ float d_one[256];
__device__ float d_b3p[128];
// permuted fragment-order weights (hi/lo)
__device__ float d_w1ph[2*9*4096],  d_w1pl[2*9*4096];
__device__ float d_w2ph[2*8*4096],  d_w2pl[2*8*4096];
__device__ float d_w3ph[2*8*4096],  d_w3pl[2*8*4096];
__device__ float d_pw1h[2*8*4096],  d_pw1l[2*8*4096];
__device__ float d_pw2h[2*8*4096],  d_pw2l[2*8*4096];
__device__ float d_hwh [1*8*4096],  d_hwl [1*8*4096];

// ---------------- output layout offsets ----------------
#define OFF_OBJ    0LL
#define OFF_CENTER 16384LL
#define OFF_SSC    40960LL
#define OFF_SRES   188416LL
#define OFF_PSIZE  630784LL
#define OFF_SEM    655360LL
#define OFF_CORN   802816LL
#define OFF_SLOG   999424LL
#define OFF_OPROB  1155072LL
#define OFF_SPROB  1163264LL

__device__ __forceinline__ uint32_t f2tf(float x) {
    uint32_t r; asm("cvt.rna.tf32.f32 %0, %1;" : "=r"(r) : "f"(x)); return r;
}
__device__ __forceinline__ uint32_t smem_u32(const void* p) {
    uint32_t a;
    asm("{ .reg .u64 t; cvta.to.shared.u64 t, %1; cvt.u32.u64 %0, t; }" : "=r"(a) : "l"(p));
    return a;
}
__device__ __forceinline__ void cp16(uint32_t s, const void* g) {
    asm volatile("cp.async.cg.shared.global [%0], [%1], 16;" :: "r"(s), "l"(g));
}
#define CP_COMMIT() asm volatile("cp.async.commit_group;" ::: "memory")
#define CP_WAIT(n)  asm volatile("cp.async.wait_group %0;" :: "n"(n) : "memory")

__device__ __forceinline__ void mma_tf32(float* c, const uint32_t* a,
                                         uint32_t b0, uint32_t b1) {
    asm volatile(
        "mma.sync.aligned.m16n8k8.row.col.f32.tf32.tf32.f32 "
        "{%0,%1,%2,%3}, {%4,%5,%6,%7}, {%8,%9}, {%0,%1,%2,%3};"
        : "+f"(c[0]), "+f"(c[1]), "+f"(c[2]), "+f"(c[3])
        : "r"(a[0]), "r"(a[1]), "r"(a[2]), "r"(a[3]), "r"(b0), "r"(b1));
}

// ============ 3xTF32 GEMM, cp.async double-buffered ============
// A: hi/lo natural row-major. B: hi/lo fragment-permuted.
// C: if Cl != null, write hi/lo split; else plain. mode 0: relu(v*s+b); 1: v+b
__global__ __launch_bounds__(256) void gemm_mma(
    const float* __restrict__ Ah, const float* __restrict__ Al, int lda,
    const float* __restrict__ Bph, const float* __restrict__ Bpl,
    float* __restrict__ Ch, float* __restrict__ Cl, int ldc,
    int nchunk,
    const float* __restrict__ scale, const float* __restrict__ bias, int mode)
{
    extern __shared__ float sm[];
    float* s_s = sm + 2*STAGEF;
    float* s_b = s_s + 128;
    const uint32_t smb = smem_u32(sm);

    const int tid = threadIdx.x;
    const int lane = tid & 31, wid = tid >> 5;
    const int wm = wid & 3, wn = wid >> 2;
    const long long m0 = (long long)blockIdx.x * 128;
    const int yb = blockIdx.y, y0 = yb * 128;
    const int lq = lane >> 2, lr = lane & 3;

    if (tid < 128) {
        s_s[tid] = (mode == 0) ? scale[y0 + tid] : 1.0f;
        s_b[tid] = bias[y0 + tid];
    }

    float acc[2][8][4];
    #pragma unroll
    for (int mt = 0; mt < 2; mt++)
        #pragma unroll
        for (int nt = 0; nt < 8; nt++)
            #pragma unroll
            for (int j = 0; j < 4; j++) acc[mt][nt][j] = 0.0f;

    const int srow = tid >> 3, sq = tid & 7;
    const long long bbase = (long long)yb * nchunk * 4096;

    // stage loader
    auto stage = [&](int kc) {
        const int st = kc & 1;
        const uint32_t sb0 = smb + st * STAGEF * 4;
        const int kt = kc * 32;
        #pragma unroll
        for (int it = 0; it < 4; it++) {
            int row = srow + it * 32;
            long long g = (m0 + row) * lda + kt + sq * 4;
            uint32_t so = sb0 + (uint32_t)(row * 144 + sq * 16);
            cp16(so, Ah + g);
            cp16(so + 4608*4, Al + g);
        }
        const long long bg = bbase + (long long)kc * 4096;
        #pragma unroll
        for (int it = 0; it < 4; it++) {
            int idx = tid + it * 256;                 // 16B unit, 0..1023
            uint32_t so = sb0 + 9216*4 + (uint32_t)(idx * 16);
            cp16(so, Bph + bg + idx * 4);
            cp16(so + 4096*4, Bpl + bg + idx * 4);
        }
    };

    stage(0); CP_COMMIT();

    for (int kc = 0; kc < nchunk; kc++) {
        if (kc + 1 < nchunk) { stage(kc + 1); CP_COMMIT(); CP_WAIT(1); }
        else CP_WAIT(0);
        __syncthreads();

        const int st = kc & 1;
        const float* sAh = sm + st * STAGEF;
        const float* sAl = sAh + 4608;
        const float* sBh = sAl + 4608;
        const float* sBl = sBh + 4096;

        #pragma unroll
        for (int k8p = 0; k8p < 2; k8p++) {
            // A fragments for both k8 of this pair, hi & lo
            uint32_t ahf[2][2][4], alf[2][2][4];   // [k8l][mt][4]
            #pragma unroll
            for (int k8l = 0; k8l < 2; k8l++) {
                const int kk = (k8p * 2 + k8l) * 8 + lr;
                #pragma unroll
                for (int mt = 0; mt < 2; mt++) {
                    int r = wm * 32 + mt * 16 + lq;
                    ahf[k8l][mt][0] = __float_as_uint(sAh[r * SAS + kk]);
                    ahf[k8l][mt][1] = __float_as_uint(sAh[(r + 8) * SAS + kk]);
                    ahf[k8l][mt][2] = __float_as_uint(sAh[r * SAS + kk + 4]);
                    ahf[k8l][mt][3] = __float_as_uint(sAh[(r + 8) * SAS + kk + 4]);
                    alf[k8l][mt][0] = __float_as_uint(sAl[r * SAS + kk]);
                    alf[k8l][mt][1] = __float_as_uint(sAl[(r + 8) * SAS + kk]);
                    alf[k8l][mt][2] = __float_as_uint(sAl[r * SAS + kk + 4]);
                    alf[k8l][mt][3] = __float_as_uint(sAl[(r + 8) * SAS + kk + 4]);
                }
            }
            // B fragments: LDS.128, packed [k8a b0,b1, k8b b0,b1]
            uint4 bh[8], bl[8];
            #pragma unroll
            for (int nt = 0; nt < 8; nt++) {
                int fo = ((k8p * 16 + wn * 8 + nt) * 32 + lane) * 4;
                bh[nt] = *(const uint4*)(sBh + fo);
                bl[nt] = *(const uint4*)(sBl + fo);
            }
            #pragma unroll
            for (int k8l = 0; k8l < 2; k8l++) {
                #pragma unroll
                for (int mt = 0; mt < 2; mt++) {
                    #pragma unroll
                    for (int nt = 0; nt < 8; nt++)
                        mma_tf32(acc[mt][nt], alf[k8l][mt],
                                 k8l ? bh[nt].z : bh[nt].x, k8l ? bh[nt].w : bh[nt].y);
                    #pragma unroll
                    for (int nt = 0; nt < 8; nt++)
                        mma_tf32(acc[mt][nt], ahf[k8l][mt],
                                 k8l ? bl[nt].z : bl[nt].x, k8l ? bl[nt].w : bl[nt].y);
                    #pragma unroll
                    for (int nt = 0; nt < 8; nt++)
                        mma_tf32(acc[mt][nt], ahf[k8l][mt],
                                 k8l ? bh[nt].z : bh[nt].x, k8l ? bh[nt].w : bh[nt].y);
                }
            }
        }
        __syncthreads();
    }

    // epilogue
    #pragma unroll
    for (int mt = 0; mt < 2; mt++) {
        long long r0 = m0 + wm * 32 + mt * 16 + lq;
        #pragma unroll
        for (int nt = 0; nt < 8; nt++) {
            int gc = wn * 64 + nt * 8 + 2 * lr;
            float s0 = s_s[gc], s1 = s_s[gc + 1];
            float b0 = s_b[gc], b1 = s_b[gc + 1];
            float v00 = acc[mt][nt][0] * s0 + b0;
            float v01 = acc[mt][nt][1] * s1 + b1;
            float v10 = acc[mt][nt][2] * s0 + b0;
            float v11 = acc[mt][nt][3] * s1 + b1;
            if (mode == 0) {
                v00 = fmaxf(v00, 0.f); v01 = fmaxf(v01, 0.f);
                v10 = fmaxf(v10, 0.f); v11 = fmaxf(v11, 0.f);
            }
            long long o0 = r0 * ldc + y0 + gc;
            long long o1 = (r0 + 8) * ldc + y0 + gc;
            if (Cl) {
                float h00 = __uint_as_float(f2tf(v00)), h01 = __uint_as_float(f2tf(v01));
                float h10 = __uint_as_float(f2tf(v10)), h11 = __uint_as_float(f2tf(v11));
                *(float2*)(Ch + o0) = make_float2(h00, h01);
                *(float2*)(Ch + o1) = make_float2(h10, h11);
                *(float2*)(Cl + o0) = make_float2(__uint_as_float(f2tf(v00 - h00)),
                                                  __uint_as_float(f2tf(v01 - h01)));
                *(float2*)(Cl + o1) = make_float2(__uint_as_float(f2tf(v10 - h10)),
                                                  __uint_as_float(f2tf(v11 - h11)));
            } else {
                *(float2*)(Ch + o0) = make_float2(v00, v01);
                *(float2*)(Ch + o1) = make_float2(v10, v11);
            }
        }
    }
}

// ---------------- weight permute (fragment order, hi/lo) ----------------
__global__ void permW_kernel(const float* __restrict__ W, int nrows, int ksrc,
                             int nkc, float* __restrict__ oh, float* __restrict__ ol) {
    int e = blockIdx.x * 256 + threadIdx.x;
    int yb = e / (nkc * 4096);
    int rem = e - yb * nkc * 4096;
    int kc = rem >> 12;
    int w = rem & 4095;
    int k8p = w >> 11, ntile = (w >> 7) & 15, lane = (w >> 2) & 31, j = w & 3;
    int o = yb * 128 + ntile * 8 + (lane >> 2);
    int k = kc * 32 + k8p * 16 + (j >> 1) * 8 + (j & 1) * 4 + (lane & 3);
    float v = (o < nrows && k < ksrc) ? W[o * ksrc + k] : 0.0f;
    float h = __uint_as_float(f2tf(v));
    oh[e] = h;
    ol[e] = __uint_as_float(f2tf(v - h));
}

__global__ void sb_kernel(const float* __restrict__ sg, const float* __restrict__ sbe,
                          const float* __restrict__ sm, const float* __restrict__ sv,
                          const float* __restrict__ pg, const float* __restrict__ pb,
                          const float* __restrict__ pm, const float* __restrict__ pv,
                          const float* __restrict__ b3) {
    int l = blockIdx.x, t = threadIdx.x;
    if (l == 5) {
        if (t < 128) d_b3p[t] = (t < OUTD) ? b3[t] : 0.0f;
        d_one[t] = 1.0f;
        return;
    }
    float g, bt, m, v;
    if (l < 3) { g = sg[l*256+t]; bt = sbe[l*256+t]; m = sm[l*256+t]; v = sv[l*256+t]; }
    else { int q = l - 3; g = pg[q*256+t]; bt = pb[q*256+t]; m = pm[q*256+t]; v = pv[q*256+t]; }
    float s = g / sqrtf(v + 1e-5f);
    d_sb[l*512 + t] = s;
    d_sb[l*512 + 256 + t] = bt - m * s;
}

// ---------------- FPS ----------------
__global__ __launch_bounds__(256) void fps_kernel(const float* __restrict__ xyz) {
    __shared__ float sx[KPTS], sy[KPTS], sz[KPTS];
    __shared__ float wv_s[8];
    __shared__ int   wi_s[8];
    __shared__ int   sfar;
    int b = blockIdx.x, tid = threadIdx.x;
    const float* base = xyz + (size_t)b * KPTS * 3;
    for (int k = tid; k < KPTS; k += 256) {
        sx[k] = base[k*3+0]; sy[k] = base[k*3+1]; sz[k] = base[k*3+2];
    }
    float dreg[8];
    #pragma unroll
    for (int j = 0; j < 8; j++) dreg[j] = 1e10f;
    int far = 0;
    int warp = tid >> 5, lane = tid & 31;
    __syncthreads();
    for (int i = 0; i < NPROP; i++) {
        float cx = sx[far], cy = sy[far], cz = sz[far];
        if (tid == 0) {
            d_newxyz[(b*NPROP+i)*3+0] = cx;
            d_newxyz[(b*NPROP+i)*3+1] = cy;
            d_newxyz[(b*NPROP+i)*3+2] = cz;
        }
        float bv = -1.0f; int bi = 0x7fffffff;
        #pragma unroll
        for (int j = 0; j < 8; j++) {
            int k = tid + j * 256;
            float dx = sx[k]-cx, dy = sy[k]-cy, dz = sz[k]-cz;
            float d = __fadd_rn(__fadd_rn(__fmul_rn(dx,dx), __fmul_rn(dy,dy)), __fmul_rn(dz,dz));
            dreg[j] = fminf(dreg[j], d);
            if (dreg[j] > bv) { bv = dreg[j]; bi = k; }
        }
        unsigned bvb = __float_as_uint(bv);                   // bv >= 0
        unsigned vmax = __reduce_max_sync(0xffffffffu, bvb);
        unsigned cand = (bvb == vmax) ? (unsigned)bi : 0x7fffffffu;
        unsigned bidx = __reduce_min_sync(0xffffffffu, cand);
        if (lane == 0) { wv_s[warp] = __uint_as_float(vmax); wi_s[warp] = (int)bidx; }
        __syncthreads();
        if (warp == 0) {
            unsigned v = (lane < 8) ? __float_as_uint(wv_s[lane]) : 0u;
            unsigned ii = (lane < 8) ? (unsigned)wi_s[lane] : 0x7fffffffu;
            unsigned vm = __reduce_max_sync(0xffffffffu, v);
            unsigned c2 = (v == vm) ? ii : 0x7fffffffu;
            unsigned idx = __reduce_min_sync(0xffffffffu, c2);
            if (lane == 0) sfar = (int)idx;
        }
        __syncthreads();
        far = sfar;
    }
}

// ---------------- ball query ----------------
__global__ __launch_bounds__(256) void bq_kernel(const float* __restrict__ xyz) {
    __shared__ float sx[KPTS], sy[KPTS], sz[KPTS];
    int b = blockIdx.x, tid = threadIdx.x;
    const float* base = xyz + (size_t)b * KPTS * 3;
    for (int k = tid; k < KPTS; k += 256) {
        sx[k] = base[k*3+0]; sy[k] = base[k*3+1]; sz[k] = base[k*3+2];
    }
    __syncthreads();
    int p = tid;
    float nx = d_newxyz[(b*NPROP+p)*3+0];
    float ny = d_newxyz[(b*NPROP+p)*3+1];
    float nz = d_newxyz[(b*NPROP+p)*3+2];
    int* dst = d_idxbuf + (b*NPROP+p)*NSAMP;
    int cnt = 0, first = 0;
    const float R2 = 0.09f;
    for (int k = 0; k < KPTS; k++) {
        float dx = sx[k]-nx, dy = sy[k]-ny, dz = sz[k]-nz;
        float d = __fadd_rn(__fadd_rn(__fmul_rn(dx,dx), __fmul_rn(dy,dy)), __fmul_rn(dz,dz));
        if (d < R2) {
            if (cnt == 0) first = k;
            dst[cnt] = k;
            if (++cnt == NSAMP) break;
        }
    }
    for (int j = cnt; j < NSAMP; j++) dst[j] = first;
}

// ---------------- feature transpose ----------------
__global__ void transpose_kernel(const float* __restrict__ in) {
    __shared__ float tile[32][33];
    int b = blockIdx.z;
    int k0 = blockIdx.x * 32, c0 = blockIdx.y * 32;
    const float* src = in + (size_t)b * CFEAT * KPTS;
    float* dst = d_featT + (size_t)b * KPTS * CFEAT;
    int tx = threadIdx.x, ty = threadIdx.y;
    #pragma unroll
    for (int i = 0; i < 4; i++)
        tile[ty + i*8][tx] = src[(size_t)(c0 + ty + i*8) * KPTS + k0 + tx];
    __syncthreads();
    #pragma unroll
    for (int i = 0; i < 4; i++)
        dst[(size_t)(k0 + ty + i*8) * CFEAT + c0 + tx] = tile[tx][ty + i*8];
}

// ---------------- gather: build Xt hi/lo ----------------
__global__ __launch_bounds__(128) void gather_kernel(const float* __restrict__ xyz) {
    int blk = blockIdx.x;            // b*256 + p
    int b = blk >> 8;
    int tid = threadIdx.x;
    __shared__ int   ks[NSAMP];
    __shared__ float cxyz[3];
    if (tid < NSAMP) ks[tid] = d_idxbuf[blk*NSAMP + tid];
    if (tid < 3)     cxyz[tid] = d_newxyz[blk*3 + tid];
    __syncthreads();
    for (int s = 0; s < NSAMP; s++) {
        int k = ks[s];
        const float* frow = d_featT + ((size_t)b * KPTS + k) * CFEAT;
        const float* prow = xyz + ((size_t)b * KPTS + k) * 3;
        size_t ro = ((size_t)blk * NSAMP + s) * K1P;
        for (int c = tid; c < K1P; c += 128) {
            float v;
            if (c < 3)        v = (prow[c] - cxyz[c]) / 0.3f;
            else if (c < 259) v = frow[c-3];
            else              v = 0.0f;
            float h = __uint_as_float(f2tf(v));
            d_xth[ro + c] = h;
            d_xtl[ro + c] = __uint_as_float(f2tf(v - h));
        }
    }
}

// ---------------- maxpool: act3 -> Y hi/lo ----------------
__global__ __launch_bounds__(256) void maxpool_kernel() {
    int blk = blockIdx.x;
    int c = threadIdx.x;
    const float* src = d_act3 + (size_t)blk * NSAMP * CFEAT;
    float m = src[c];
    #pragma unroll
    for (int s = 1; s < NSAMP; s++) m = fmaxf(m, src[s*CFEAT + c]);
    float h = __uint_as_float(f2tf(m));
    d_yh[(size_t)blk * CFEAT + c] = h;
    d_yl[(size_t)blk * CFEAT + c] = __uint_as_float(f2tf(m - h));
}

// ---------------- decode head ----------------
__global__ __launch_bounds__(256) void decode_kernel(const float* __restrict__ msa,
                                                     float* __restrict__ out) {
    int g = blockIdx.x * 256 + threadIdx.x;
    if (g >= PROPROW) return;
    const float* nt = d_net + (size_t)g * 128;
    const float* nx = d_newxyz + (size_t)g * 3;

    float obj0 = nt[0], obj1 = nt[1];
    out[OFF_OBJ + 2*g + 0] = obj0;
    out[OFF_OBJ + 2*g + 1] = obj1;

    float cen[3];
    #pragma unroll
    for (int c = 0; c < 3; c++) {
        cen[c] = nx[c] + nt[2 + c];
        out[OFF_CENTER + 3*g + c] = cen[c];
    }

    float bestv = -1e30f; int best = 0;
    #pragma unroll
    for (int j = 0; j < 18; j++) {
        float s = nt[29 + j];
        out[OFF_SSC + 18*g + j] = s;
        if (s > bestv) { bestv = s; best = j; }
    }

    #pragma unroll
    for (int j = 0; j < 18; j++)
        #pragma unroll
        for (int c = 0; c < 3; c++)
            out[OFF_SRES + 54*g + j*3 + c] = nt[47 + j*3 + c] * msa[j*3 + c];

    float ps[3];
    #pragma unroll
    for (int c = 0; c < 3; c++) {
        ps[c] = nt[47 + best*3 + c] * msa[best*3 + c] + msa[best*3 + c];
        out[OFF_PSIZE + 3*g + c] = ps[c];
    }

    float mx = -1e30f;
    #pragma unroll
    for (int j = 0; j < 18; j++) {
        float s = nt[101 + j];
        out[OFF_SEM  + 18*g + j] = s;
        out[OFF_SLOG + 19*g + j] = s;
        mx = fmaxf(mx, s);
    }
    float e[18], sum = 0.0f;
    #pragma unroll
    for (int j = 0; j < 18; j++) { e[j] = expf(nt[101 + j] - mx); sum += e[j]; }
    #pragma unroll
    for (int j = 0; j < 18; j++) out[OFF_SPROB + 18*g + j] = e[j] / sum;

    out[OFF_SLOG + 19*g + 18] = (obj0 <= obj1) ? 0.0f : 1e10f;

    float m2 = fmaxf(obj0, obj1);
    float e0 = expf(obj0 - m2), e1 = expf(obj1 - m2);
    out[OFF_OPROB + g] = e1 / (e0 + e1);

    float cc0 = cen[0], cc1 = cen[2], cc2 = -cen[1];
    const float sxv[8] = {1,1,-1,-1,1,1,-1,-1};
    const float syv[8] = {1,1,1,1,-1,-1,-1,-1};
    const float szv[8] = {1,-1,-1,1,1,-1,-1,1};
    #pragma unroll
    for (int k = 0; k < 8; k++) {
        out[OFF_CORN + 24*g + k*3 + 0] = cc0 + ps[0] * sxv[k] * 0.5f;
        out[OFF_CORN + 24*g + k*3 + 1] = cc1 + ps[2] * syv[k] * 0.5f;
        out[OFF_CORN + 24*g + k*3 + 2] = cc2 + ps[1] * szv[k] * 0.5f;
    }
}

// ---------------- launch ----------------
extern "C" void kernel_launch(void* const* d_in, const int* in_sizes, int n_in,
                              void* d_out, int out_size) {
    const float* xyz      = (const float*)d_in[0];
    const float* features = (const float*)d_in[1];
    const float* sa_w1    = (const float*)d_in[2];
    const float* sa_w2    = (const float*)d_in[3];
    const float* sa_w3    = (const float*)d_in[4];
    const float* sa_gamma = (const float*)d_in[5];
    const float* sa_beta  = (const float*)d_in[6];
    const float* sa_mean  = (const float*)d_in[7];
    const float* sa_var   = (const float*)d_in[8];
    const float* p_w1     = (const float*)d_in[9];
    const float* p_w2     = (const float*)d_in[10];
    const float* p_w3     = (const float*)d_in[11];
    const float* p_b3     = (const float*)d_in[12];
    const float* p_gamma  = (const float*)d_in[13];
    const float* p_beta   = (const float*)d_in[14];
    const float* p_mean   = (const float*)d_in[15];
    const float* p_var    = (const float*)d_in[16];
    const float* msa      = (const float*)d_in[17];
    float* out = (float*)d_out;

    #define GA(sym) ({ void* _p; cudaGetSymbolAddress(&_p, sym); (float*)_p; })
    float* XTH = GA(d_xth); float* XTL = GA(d_xtl);
    float* A1H = GA(d_a1h); float* A1L = GA(d_a1l);
    float* A2H = GA(d_a2h); float* A2L = GA(d_a2l);
    float* A3  = GA(d_act3);
    float* YH  = GA(d_yh);  float* YL  = GA(d_yl);
    float* P1H = GA(d_p1h); float* P1L = GA(d_p1l);
    float* P2H = GA(d_p2h); float* P2L = GA(d_p2l);
    float* NET = GA(d_net);
    float* SB  = GA(d_sb);  float* ONE = GA(d_one); float* B3P = GA(d_b3p);
    float* W1H = GA(d_w1ph); float* W1L = GA(d_w1pl);
    float* W2H = GA(d_w2ph); float* W2L = GA(d_w2pl);
    float* W3H = GA(d_w3ph); float* W3L = GA(d_w3pl);
    float* Q1H = GA(d_pw1h); float* Q1L = GA(d_pw1l);
    float* Q2H = GA(d_pw2h); float* Q2L = GA(d_pw2l);
    float* HWH = GA(d_hwh);  float* HWL = GA(d_hwl);
    #undef GA

    cudaFuncSetAttribute(gemm_mma, cudaFuncAttributeMaxDynamicSharedMemorySize, GEMM_SMEM);

    permW_kernel<<<2*9*16, 256>>>(sa_w1, 256, 259, 9, W1H, W1L);
    permW_kernel<<<2*8*16, 256>>>(sa_w2, 256, 256, 8, W2H, W2L);
    permW_kernel<<<2*8*16, 256>>>(sa_w3, 256, 256, 8, W3H, W3L);
    permW_kernel<<<2*8*16, 256>>>(p_w1, 256, 256, 8, Q1H, Q1L);
    permW_kernel<<<2*8*16, 256>>>(p_w2, 256, 256, 8, Q2H, Q2L);
    permW_kernel<<<1*8*16, 256>>>(p_w3, OUTD, 256, 8, HWH, HWL);
    sb_kernel<<<6, 256>>>(sa_gamma, sa_beta, sa_mean, sa_var,
                          p_gamma, p_beta, p_mean, p_var, p_b3);
    fps_kernel<<<BB, 256>>>(xyz);
    bq_kernel<<<BB, 256>>>(xyz);
    transpose_kernel<<<dim3(KPTS/32, CFEAT/32, BB), dim3(32, 8)>>>(features);
    gather_kernel<<<PROPROW, 128>>>(xyz);

    // SA layers
    gemm_mma<<<dim3(TOTROW/128, 2), 256, GEMM_SMEM>>>(XTH, XTL, K1P, W1H, W1L,
        A1H, A1L, 256, 9, SB + 0*512, SB + 0*512 + 256, 0);
    gemm_mma<<<dim3(TOTROW/128, 2), 256, GEMM_SMEM>>>(A1H, A1L, 256, W2H, W2L,
        A2H, A2L, 256, 8, SB + 1*512, SB + 1*512 + 256, 0);
    gemm_mma<<<dim3(TOTROW/128, 2), 256, GEMM_SMEM>>>(A2H, A2L, 256, W3H, W3L,
        A3, (float*)0, 256, 8, SB + 2*512, SB + 2*512 + 256, 0);

    maxpool_kernel<<<PROPROW, 256>>>();

    // proposal layers
    gemm_mma<<<dim3(PROPROW/128, 2), 256, GEMM_SMEM>>>(YH, YL, 256, Q1H, Q1L,
        P1H, P1L, 256, 8, SB + 3*512, SB + 3*512 + 256, 0);
    gemm_mma<<<dim3(PROPROW/128, 2), 256, GEMM_SMEM>>>(P1H, P1L, 256, Q2H, Q2L,
        P2H, P2L, 256, 8, SB + 4*512, SB + 4*512 + 256, 0);
    gemm_mma<<<dim3(PROPROW/128, 1), 256, GEMM_SMEM>>>(P2H, P2L, 256, HWH, HWL,
        NET, (float*)0, 128, 8, ONE, B3P, 1);

    decode_kernel<<<PROPROW/256, 256>>>(msa, out);
}